// round 4
// baseline (speedup 1.0000x reference)
#include <cuda_runtime.h>
#include <math.h>

#define NN 50000
#define NE 800000
#define DIN 128
#define HID 192

// ---- scratch (device globals; allocation APIs are forbidden) ----
__device__ float g_h[NN * HID];      // node features
__device__ float g_m[NN * HID];      // transformed features / head p buffer
__device__ float g_p2[NN * 96];      // pos-head intermediate
__device__ float g_r[NN * 96];       // radius-head intermediate
__device__ float g_dinv[NN];         // 1/sqrt(deg) (deg includes self-loop)
__device__ int   g_degi[NN];         // in-degree (edges only)
__device__ int   g_cur[NN];          // CSR fill cursors
__device__ int   g_off[NN + 1];      // CSR row offsets
__device__ int   g_csr_src[NE];      // CSR: source node per edge
__device__ float g_csr_w[NE];        // CSR: dinv[src]*dinv[dst] per edge

// ---------------------------------------------------------------------------
// Degree / CSR construction (all global refs are device-side: safe)
// ---------------------------------------------------------------------------
__global__ void zero_counts_kernel() {
    int i = blockIdx.x * blockDim.x + threadIdx.x;
    if (i < NN) { g_degi[i] = 0; g_cur[i] = 0; }
}

__global__ void deg_count_kernel(const int* __restrict__ dst) {
    int e = blockIdx.x * blockDim.x + threadIdx.x;
    if (e < NE) atomicAdd(&g_degi[dst[e]], 1);
}

// single-block chunked exclusive scan of g_degi -> g_off (50k elements)
__global__ void scan_kernel() {
    __shared__ int s[1024];
    __shared__ int carry_s;
    int tid = threadIdx.x;
    if (tid == 0) carry_s = 0;
    __syncthreads();
    for (int base = 0; base < NN; base += 1024) {
        int i = base + tid;
        int v = (i < NN) ? g_degi[i] : 0;
        s[tid] = v;
        __syncthreads();
        #pragma unroll
        for (int off = 1; off < 1024; off <<= 1) {
            int t = (tid >= off) ? s[tid - off] : 0;
            __syncthreads();
            s[tid] += t;
            __syncthreads();
        }
        int carry = carry_s;
        if (i < NN) g_off[i] = carry + s[tid] - v;   // exclusive
        __syncthreads();
        if (tid == 1023) carry_s += s[1023];
        __syncthreads();
    }
    if (tid == 0) g_off[NN] = carry_s;
}

__global__ void dinv_kernel() {
    int i = blockIdx.x * blockDim.x + threadIdx.x;
    if (i < NN) g_dinv[i] = rsqrtf((float)(g_degi[i] + 1));  // +1 self-loop
}

__global__ void csr_fill_kernel(const int* __restrict__ src, const int* __restrict__ dst) {
    int e = blockIdx.x * blockDim.x + threadIdx.x;
    if (e >= NE) return;
    int s = src[e], d = dst[e];
    int pos = g_off[d] + atomicAdd(&g_cur[d], 1);
    g_csr_src[pos] = s;
    g_csr_w[pos] = g_dinv[s] * g_dinv[d];
}

// ---------------------------------------------------------------------------
// Tiled fp32 GEMM: C[M,N] = A[M,K] @ B[K,N] (+bias) (+relu)
// BM=64, BN=64, BK=16, 256 threads, 4x4 per thread. K multiple of 16.
// A, B, C are proper DEVICE pointers (resolved via cudaGetSymbolAddress).
// ---------------------------------------------------------------------------
__global__ __launch_bounds__(256) void gemm_bias_kernel(
    const float* __restrict__ A, const float* __restrict__ B,
    const float* __restrict__ bias, float* __restrict__ C,
    int M, int N, int K, int relu)
{
    const int BM = 64, BN = 64, BK = 16;
    __shared__ float As[BK][BM + 1];
    __shared__ float Bs[BK][BN];

    int tx = threadIdx.x & 15;
    int ty = threadIdx.x >> 4;
    int row0 = blockIdx.y * BM;
    int col0 = blockIdx.x * BN;

    float acc[4][4] = {};

    for (int k0 = 0; k0 < K; k0 += BK) {
        for (int i = threadIdx.x; i < BM * BK; i += 256) {
            int r = i >> 4, c = i & 15;
            int gr = row0 + r;
            As[c][r] = (gr < M) ? A[(size_t)gr * K + (k0 + c)] : 0.0f;
        }
        for (int i = threadIdx.x; i < BK * BN; i += 256) {
            int r = i >> 6, c = i & 63;
            int gc = col0 + c;
            Bs[r][c] = (gc < N) ? B[(size_t)(k0 + r) * N + gc] : 0.0f;
        }
        __syncthreads();

        #pragma unroll
        for (int kk = 0; kk < BK; kk++) {
            float a[4], b[4];
            #pragma unroll
            for (int i = 0; i < 4; i++) a[i] = As[kk][ty * 4 + i];
            #pragma unroll
            for (int j = 0; j < 4; j++) b[j] = Bs[kk][tx * 4 + j];
            #pragma unroll
            for (int i = 0; i < 4; i++)
                #pragma unroll
                for (int j = 0; j < 4; j++)
                    acc[i][j] = fmaf(a[i], b[j], acc[i][j]);
        }
        __syncthreads();
    }

    #pragma unroll
    for (int i = 0; i < 4; i++) {
        int gr = row0 + ty * 4 + i;
        if (gr >= M) continue;
        #pragma unroll
        for (int j = 0; j < 4; j++) {
            int gc = col0 + tx * 4 + j;
            if (gc >= N) continue;
            float v = acc[i][j];
            if (bias) v += bias[gc];
            if (relu) v = fmaxf(v, 0.0f);
            C[(size_t)gr * N + gc] = v;
        }
    }
}

// ---------------------------------------------------------------------------
// Fused GCN aggregation (deterministic gather, no float atomics):
//   h[n] += relu( dinv[n]^2*m[n] + sum_{e:dst=n} w_e * m[src_e] + convB )
// 16 threads per node; lane owns float4 columns {lane, lane+16, lane+32}.
// All global refs are device-side: safe.
// ---------------------------------------------------------------------------
__device__ __forceinline__ void f4_fma(float4& a, float w, const float4 v) {
    a.x = fmaf(w, v.x, a.x); a.y = fmaf(w, v.y, a.y);
    a.z = fmaf(w, v.z, a.z); a.w = fmaf(w, v.w, a.w);
}

__global__ __launch_bounds__(256) void gcn_agg_kernel(const float* __restrict__ convB) {
    int t = blockIdx.x * blockDim.x + threadIdx.x;
    int node = t >> 4;
    int lane = t & 15;
    if (node >= NN) return;

    float di = g_dinv[node];
    float w0 = di * di;
    const float4* mrow = (const float4*)(g_m + (size_t)node * HID);
    float4 a0 = mrow[lane], a1 = mrow[lane + 16], a2 = mrow[lane + 32];
    a0.x *= w0; a0.y *= w0; a0.z *= w0; a0.w *= w0;
    a1.x *= w0; a1.y *= w0; a1.z *= w0; a1.w *= w0;
    a2.x *= w0; a2.y *= w0; a2.z *= w0; a2.w *= w0;

    int beg = g_off[node], end = g_off[node + 1];
    for (int j = beg; j < end; j++) {
        int s = g_csr_src[j];
        float w = g_csr_w[j];
        const float4* ms = (const float4*)(g_m + (size_t)s * HID);
        f4_fma(a0, w, ms[lane]);
        f4_fma(a1, w, ms[lane + 16]);
        f4_fma(a2, w, ms[lane + 32]);
    }

    const float4* b4 = (const float4*)convB;
    float4 b0 = b4[lane], b1 = b4[lane + 16], b2 = b4[lane + 32];
    float4* hrow = (float4*)(g_h + (size_t)node * HID);
    float4 h0 = hrow[lane], h1 = hrow[lane + 16], h2 = hrow[lane + 32];
    h0.x += fmaxf(a0.x + b0.x, 0.f); h0.y += fmaxf(a0.y + b0.y, 0.f);
    h0.z += fmaxf(a0.z + b0.z, 0.f); h0.w += fmaxf(a0.w + b0.w, 0.f);
    h1.x += fmaxf(a1.x + b1.x, 0.f); h1.y += fmaxf(a1.y + b1.y, 0.f);
    h1.z += fmaxf(a1.z + b1.z, 0.f); h1.w += fmaxf(a1.w + b1.w, 0.f);
    h2.x += fmaxf(a2.x + b2.x, 0.f); h2.y += fmaxf(a2.y + b2.y, 0.f);
    h2.z += fmaxf(a2.z + b2.z, 0.f); h2.w += fmaxf(a2.w + b2.w, 0.f);
    hrow[lane] = h0; hrow[lane + 16] = h1; hrow[lane + 32] = h2;
}

// ---------------------------------------------------------------------------
// Final head: pos = p2 @ Wp3 + bp3 (96->2); radius = sigmoid(r @ Wr2 + br2);
// coords = pos / (|pos| + 1e-8) * radius.  One warp per node.
// ---------------------------------------------------------------------------
__global__ void head_final_kernel(
    const float* __restrict__ Wp3, const float* __restrict__ bp3,
    const float* __restrict__ Wr2, const float* __restrict__ br2,
    float* __restrict__ out)
{
    int w = (blockIdx.x * blockDim.x + threadIdx.x) >> 5;
    int lane = threadIdx.x & 31;
    if (w >= NN) return;
    const float* p2 = g_p2 + (size_t)w * 96;
    const float* rr = g_r + (size_t)w * 96;
    float a0 = 0.0f, a1 = 0.0f, ar = 0.0f;
    #pragma unroll
    for (int i = lane; i < 96; i += 32) {
        float v = p2[i];
        a0 = fmaf(v, Wp3[i * 2 + 0], a0);
        a1 = fmaf(v, Wp3[i * 2 + 1], a1);
        ar = fmaf(rr[i], Wr2[i], ar);
    }
    #pragma unroll
    for (int o = 16; o; o >>= 1) {
        a0 += __shfl_down_sync(0xFFFFFFFFu, a0, o);
        a1 += __shfl_down_sync(0xFFFFFFFFu, a1, o);
        ar += __shfl_down_sync(0xFFFFFFFFu, ar, o);
    }
    if (lane == 0) {
        float p0 = a0 + bp3[0];
        float p1 = a1 + bp3[1];
        float rad = 1.0f / (1.0f + expf(-(ar + br2[0])));
        float nrm = sqrtf(p0 * p0 + p1 * p1) + 1e-8f;
        float scale = rad / nrm;
        out[w * 2 + 0] = p0 * scale;
        out[w * 2 + 1] = p1 * scale;
    }
}

// ---------------------------------------------------------------------------
extern "C" void kernel_launch(void* const* d_in, const int* in_sizes, int n_in,
                              void* d_out, int out_size)
{
    const float *x, *Wp, *bp, *convW, *convB, *Wp1, *bp1, *Wp2, *bp2, *Wp3, *bp3;
    const float *Wr1, *br1, *Wr2, *br2;
    const int *ei;

    if (in_sizes[0] == NN * DIN) {
        // dict order: x, edge_index, Wp, bp, convW, convB, Wp1, bp1, Wp2, bp2,
        //             Wp3, bp3, Wr1, br1, Wr2, br2
        x     = (const float*)d_in[0];
        ei    = (const int*)  d_in[1];
        Wp    = (const float*)d_in[2];  bp    = (const float*)d_in[3];
        convW = (const float*)d_in[4];  convB = (const float*)d_in[5];
        Wp1   = (const float*)d_in[6];  bp1   = (const float*)d_in[7];
        Wp2   = (const float*)d_in[8];  bp2   = (const float*)d_in[9];
        Wp3   = (const float*)d_in[10]; bp3   = (const float*)d_in[11];
        Wr1   = (const float*)d_in[12]; br1   = (const float*)d_in[13];
        Wr2   = (const float*)d_in[14]; br2   = (const float*)d_in[15];
    } else {
        // alphabetical (ASCII) order: Wp, Wp1, Wp2, Wp3, Wr1, Wr2, bp, bp1,
        //   bp2, bp3, br1, br2, convB, convW, edge_index, x
        Wp    = (const float*)d_in[0];
        Wp1   = (const float*)d_in[1];
        Wp2   = (const float*)d_in[2];
        Wp3   = (const float*)d_in[3];
        Wr1   = (const float*)d_in[4];
        Wr2   = (const float*)d_in[5];
        bp    = (const float*)d_in[6];
        bp1   = (const float*)d_in[7];
        bp2   = (const float*)d_in[8];
        bp3   = (const float*)d_in[9];
        br1   = (const float*)d_in[10];
        br2   = (const float*)d_in[11];
        convB = (const float*)d_in[12];
        convW = (const float*)d_in[13];
        ei    = (const int*)  d_in[14];
        x     = (const float*)d_in[15];
    }
    float* out = (float*)d_out;

    // CRITICAL: resolve device-global scratch to real DEVICE pointers.
    // A bare `g_h` in host code is the host-side shadow symbol — on GB300
    // (ATS-coherent) kernels silently write host memory through it.
    float *p_h, *p_m, *p_p2, *p_r;
    cudaGetSymbolAddress((void**)&p_h,  g_h);
    cudaGetSymbolAddress((void**)&p_m,  g_m);
    cudaGetSymbolAddress((void**)&p_p2, g_p2);
    cudaGetSymbolAddress((void**)&p_r,  g_r);

    const int* src = ei;
    const int* dst = ei + NE;

    // CSR build
    zero_counts_kernel<<<(NN + 255) / 256, 256>>>();
    deg_count_kernel<<<(NE + 255) / 256, 256>>>(dst);
    scan_kernel<<<1, 1024>>>();
    dinv_kernel<<<(NN + 255) / 256, 256>>>();
    csr_fill_kernel<<<(NE + 255) / 256, 256>>>(src, dst);

    dim3 g192(3, (NN + 63) / 64);
    dim3 g96(2, (NN + 63) / 64);

    // input projection: h = x @ Wp + bp
    gemm_bias_kernel<<<g192, 256>>>(x, Wp, bp, p_h, NN, HID, DIN, 0);

    // 4 GCN layers
    for (int l = 0; l < 4; l++) {
        gemm_bias_kernel<<<g192, 256>>>(p_h, convW + (size_t)l * HID * HID,
                                        nullptr, p_m, NN, HID, HID, 0);
        gcn_agg_kernel<<<(NN * 16 + 255) / 256, 256>>>(convB + (size_t)l * HID);
    }

    // heads
    gemm_bias_kernel<<<g192, 256>>>(p_h, Wp1, bp1, p_m, NN, HID, HID, 1);
    gemm_bias_kernel<<<g96, 256>>>(p_m, Wp2, bp2, p_p2, NN, 96, HID, 1);
    gemm_bias_kernel<<<g96, 256>>>(p_h, Wr1, br1, p_r, NN, 96, HID, 1);
    head_final_kernel<<<(NN * 32 + 255) / 256, 256>>>(Wp3, bp3, Wr2, br2, out);
}

// round 5
// speedup vs baseline: 1.6292x; 1.6292x over previous
#include <cuda_runtime.h>
#include <cuda_bf16.h>
#include <math.h>
#include <stdint.h>

#define NN 50000
#define NE 800000
#define DIN 128
#define HID 192

// ---- scratch (device globals; allocation APIs are forbidden) ----
__device__ float g_h[NN * HID];
__device__ float g_m[NN * HID];
__device__ float g_p2[NN * 96];
__device__ float g_r[NN * 96];
__device__ float g_dinv[NN];
__device__ int   g_degi[NN];
__device__ int   g_cur[NN];
__device__ int   g_off[NN + 1];
__device__ int   g_csr_src[NE];
__device__ float g_csr_w[NE];

// split-bf16 operand buffers
__device__ __nv_bfloat16 g_x_hi[NN * DIN], g_x_lo[NN * DIN];
__device__ __nv_bfloat16 g_h_hi[NN * HID], g_h_lo[NN * HID];
__device__ __nv_bfloat16 g_p_hi[NN * HID], g_p_lo[NN * HID];

// transposed split weights, [N,K] row-major each, packed into one buffer
#define OW_P    0        // Wp_t  192x128
#define OW_CONV 24576    // conv_t 4 x 192x192
#define OW_P1   172032   // Wp1_t 192x192
#define OW_P2   208896   // Wp2_t 96x192
#define OW_R1   227328   // Wr1_t 96x192
#define OW_TOT  245760
__device__ __nv_bfloat16 g_wt_hi[OW_TOT], g_wt_lo[OW_TOT];

// ---------------------------------------------------------------------------
// Degree / CSR construction (identical to passing R3)
// ---------------------------------------------------------------------------
__global__ void zero_counts_kernel() {
    int i = blockIdx.x * blockDim.x + threadIdx.x;
    if (i < NN) { g_degi[i] = 0; g_cur[i] = 0; }
}

__global__ void deg_count_kernel(const int* __restrict__ dst) {
    int e = blockIdx.x * blockDim.x + threadIdx.x;
    if (e < NE) atomicAdd(&g_degi[dst[e]], 1);
}

__global__ void scan_kernel() {
    __shared__ int s[1024];
    __shared__ int carry_s;
    int tid = threadIdx.x;
    if (tid == 0) carry_s = 0;
    __syncthreads();
    for (int base = 0; base < NN; base += 1024) {
        int i = base + tid;
        int v = (i < NN) ? g_degi[i] : 0;
        s[tid] = v;
        __syncthreads();
        #pragma unroll
        for (int off = 1; off < 1024; off <<= 1) {
            int t = (tid >= off) ? s[tid - off] : 0;
            __syncthreads();
            s[tid] += t;
            __syncthreads();
        }
        int carry = carry_s;
        if (i < NN) g_off[i] = carry + s[tid] - v;
        __syncthreads();
        if (tid == 1023) carry_s += s[1023];
        __syncthreads();
    }
    if (tid == 0) g_off[NN] = carry_s;
}

__global__ void dinv_kernel() {
    int i = blockIdx.x * blockDim.x + threadIdx.x;
    if (i < NN) g_dinv[i] = rsqrtf((float)(g_degi[i] + 1));
}

__global__ void csr_fill_kernel(const int* __restrict__ src, const int* __restrict__ dst) {
    int e = blockIdx.x * blockDim.x + threadIdx.x;
    if (e >= NE) return;
    int s = src[e], d = dst[e];
    int pos = g_off[d] + atomicAdd(&g_cur[d], 1);
    g_csr_src[pos] = s;
    g_csr_w[pos] = g_dinv[s] * g_dinv[d];
}

// ---------------------------------------------------------------------------
// Operand prep: split fp32 -> (hi, lo) bf16
// ---------------------------------------------------------------------------
__global__ void split_kernel(const float* __restrict__ in,
                             __nv_bfloat16* __restrict__ oh,
                             __nv_bfloat16* __restrict__ ol, int n) {
    int i = blockIdx.x * blockDim.x + threadIdx.x;
    if (i >= n) return;
    float v = in[i];
    __nv_bfloat16 h = __float2bfloat16(v);
    oh[i] = h;
    ol[i] = __float2bfloat16(v - __bfloat162float(h));
}

// W [K,N] fp32 row-major -> out [N,K] bf16 (hi, lo)
__global__ void tsplit_kernel(const float* __restrict__ W,
                              __nv_bfloat16* __restrict__ oh,
                              __nv_bfloat16* __restrict__ ol, int K, int N) {
    int idx = blockIdx.x * blockDim.x + threadIdx.x;
    if (idx >= K * N) return;
    int k = idx / N, n = idx % N;
    float v = W[idx];
    __nv_bfloat16 h = __float2bfloat16(v);
    oh[(size_t)n * K + k] = h;
    ol[(size_t)n * K + k] = __float2bfloat16(v - __bfloat162float(h));
}

// ---------------------------------------------------------------------------
// Split-bf16 tensor-core GEMM: C[M,N] = (Ah+Al)[M,K] @ (Bh+Bl)^T, B as [N,K].
// 3-product: Ah*Bh + Ah*Bl + Al*Bh, fp32 accum (mma.sync m16n8k16 bf16).
// Block: 256 thr = 8 warps (4 M x 2 N). Tile M=128, full N. BK=32, pad-40 rows.
// ---------------------------------------------------------------------------
#define MMA_BF16(d, a, b0_, b1_)                                              \
    asm volatile("mma.sync.aligned.m16n8k16.row.col.f32.bf16.bf16.f32 "       \
        "{%0,%1,%2,%3}, {%4,%5,%6,%7}, {%8,%9}, {%0,%1,%2,%3};"               \
        : "+f"((d)[0]), "+f"((d)[1]), "+f"((d)[2]), "+f"((d)[3])              \
        : "r"((a)[0]), "r"((a)[1]), "r"((a)[2]), "r"((a)[3]),                 \
          "r"(b0_), "r"(b1_))

__device__ __forceinline__ void store_pair(
    float* Cf, __nv_bfloat16* Ch, __nv_bfloat16* Cl,
    size_t idx, float v0, float v1)
{
    if (Cf) *(float2*)(Cf + idx) = make_float2(v0, v1);
    if (Ch) {
        __nv_bfloat16 h0 = __float2bfloat16(v0), h1 = __float2bfloat16(v1);
        __nv_bfloat162 hp; hp.x = h0; hp.y = h1;
        *(__nv_bfloat162*)(Ch + idx) = hp;
        __nv_bfloat162 lp;
        lp.x = __float2bfloat16(v0 - __bfloat162float(h0));
        lp.y = __float2bfloat16(v1 - __bfloat162float(h1));
        *(__nv_bfloat162*)(Cl + idx) = lp;
    }
}

template <int NF>   // n-fragments of 8 per warp-half: N = NF*16
__global__ __launch_bounds__(256, 1) void gemm_tc(
    const __nv_bfloat16* __restrict__ Ah, const __nv_bfloat16* __restrict__ Al,
    const __nv_bfloat16* __restrict__ Bh, const __nv_bfloat16* __restrict__ Bl,
    const float* __restrict__ bias, int relu,
    float* __restrict__ Cf, __nv_bfloat16* __restrict__ Ch,
    __nv_bfloat16* __restrict__ Cl, int M, int K)
{
    const int N = NF * 16;
    extern __shared__ __nv_bfloat16 smem[];
    __nv_bfloat16* sAh = smem;                 // 128 x pad40
    __nv_bfloat16* sAl = sAh + 128 * 40;
    __nv_bfloat16* sBh = sAl + 128 * 40;       // N x pad40
    __nv_bfloat16* sBl = sBh + N * 40;

    int tid = threadIdx.x, w = tid >> 5, lane = tid & 31;
    int row0 = blockIdx.x * 128;
    int mbase = (w & 3) * 32;
    int nbase = (w >> 2) * (NF * 8);
    int lr = lane >> 2;            // 0..7
    int lc = (lane & 3) * 2;       // 0,2,4,6

    float acc[2][NF][4];
    #pragma unroll
    for (int a = 0; a < 2; a++)
        #pragma unroll
        for (int b = 0; b < NF; b++)
            #pragma unroll
            for (int c = 0; c < 4; c++) acc[a][b][c] = 0.0f;

    int nkc = K >> 5;
    for (int kc = 0; kc < nkc; kc++) {
        // A tiles: 128 rows x 32 cols = 512 uint4 per matrix
        for (int u = tid; u < 512; u += 256) {
            int r = u >> 2, kp = u & 3;
            int gr = row0 + r;
            uint4 vh = make_uint4(0, 0, 0, 0), vl = make_uint4(0, 0, 0, 0);
            if (gr < M) {
                vh = *(const uint4*)(Ah + (size_t)gr * K + kc * 32 + kp * 8);
                vl = *(const uint4*)(Al + (size_t)gr * K + kc * 32 + kp * 8);
            }
            *(uint4*)(sAh + r * 40 + kp * 8) = vh;
            *(uint4*)(sAl + r * 40 + kp * 8) = vl;
        }
        // B tiles: N rows x 32 cols
        for (int u = tid; u < N * 4; u += 256) {
            int r = u >> 2, kp = u & 3;
            *(uint4*)(sBh + r * 40 + kp * 8) =
                *(const uint4*)(Bh + (size_t)r * K + kc * 32 + kp * 8);
            *(uint4*)(sBl + r * 40 + kp * 8) =
                *(const uint4*)(Bl + (size_t)r * K + kc * 32 + kp * 8);
        }
        __syncthreads();

        #pragma unroll
        for (int ks = 0; ks < 2; ks++) {
            int kx = ks * 16 + lc;
            uint32_t ahf[2][4], alf[2][4];
            #pragma unroll
            for (int mf = 0; mf < 2; mf++) {
                int mr = mbase + mf * 16 + lr;
                ahf[mf][0] = *(const uint32_t*)(sAh + mr * 40 + kx);
                ahf[mf][1] = *(const uint32_t*)(sAh + (mr + 8) * 40 + kx);
                ahf[mf][2] = *(const uint32_t*)(sAh + mr * 40 + kx + 8);
                ahf[mf][3] = *(const uint32_t*)(sAh + (mr + 8) * 40 + kx + 8);
                alf[mf][0] = *(const uint32_t*)(sAl + mr * 40 + kx);
                alf[mf][1] = *(const uint32_t*)(sAl + (mr + 8) * 40 + kx);
                alf[mf][2] = *(const uint32_t*)(sAl + mr * 40 + kx + 8);
                alf[mf][3] = *(const uint32_t*)(sAl + (mr + 8) * 40 + kx + 8);
            }
            #pragma unroll
            for (int nf = 0; nf < NF; nf++) {
                int nr = nbase + nf * 8 + lr;
                uint32_t bh0 = *(const uint32_t*)(sBh + nr * 40 + kx);
                uint32_t bh1 = *(const uint32_t*)(sBh + nr * 40 + kx + 8);
                uint32_t bl0 = *(const uint32_t*)(sBl + nr * 40 + kx);
                uint32_t bl1 = *(const uint32_t*)(sBl + nr * 40 + kx + 8);
                #pragma unroll
                for (int mf = 0; mf < 2; mf++) {
                    MMA_BF16(acc[mf][nf], ahf[mf], bh0, bh1);
                    MMA_BF16(acc[mf][nf], ahf[mf], bl0, bl1);
                    MMA_BF16(acc[mf][nf], alf[mf], bh0, bh1);
                }
            }
        }
        __syncthreads();
    }

    // epilogue
    #pragma unroll
    for (int mf = 0; mf < 2; mf++) {
        int r0 = row0 + mbase + mf * 16 + lr;
        #pragma unroll
        for (int nf = 0; nf < NF; nf++) {
            int col = nbase + nf * 8 + lc;
            float b0 = 0.0f, b1 = 0.0f;
            if (bias) { b0 = bias[col]; b1 = bias[col + 1]; }
            float v0 = acc[mf][nf][0] + b0, v1 = acc[mf][nf][1] + b1;
            float v2 = acc[mf][nf][2] + b0, v3 = acc[mf][nf][3] + b1;
            if (relu) {
                v0 = fmaxf(v0, 0.f); v1 = fmaxf(v1, 0.f);
                v2 = fmaxf(v2, 0.f); v3 = fmaxf(v3, 0.f);
            }
            if (r0 < M)     store_pair(Cf, Ch, Cl, (size_t)r0 * N + col, v0, v1);
            if (r0 + 8 < M) store_pair(Cf, Ch, Cl, (size_t)(r0 + 8) * N + col, v2, v3);
        }
    }
}

// ---------------------------------------------------------------------------
// Fused GCN aggregation (deterministic gather) + residual + relu + bf16 split:
//   h[n] += relu( dinv[n]^2*m[n] + sum_{e:dst=n} w_e*m[src_e] + convB )
//   also writes h_hi/h_lo for the next tensor-core GEMM.
// ---------------------------------------------------------------------------
__device__ __forceinline__ void f4_fma(float4& a, float w, const float4 v) {
    a.x = fmaf(w, v.x, a.x); a.y = fmaf(w, v.y, a.y);
    a.z = fmaf(w, v.z, a.z); a.w = fmaf(w, v.w, a.w);
}

__device__ __forceinline__ void split_store4(size_t base, float4 v) {
    float vv[4] = {v.x, v.y, v.z, v.w};
    __nv_bfloat16 hh[4], ll[4];
    #pragma unroll
    for (int i = 0; i < 4; i++) {
        hh[i] = __float2bfloat16(vv[i]);
        ll[i] = __float2bfloat16(vv[i] - __bfloat162float(hh[i]));
    }
    *(uint2*)(g_h_hi + base) = *(uint2*)hh;
    *(uint2*)(g_h_lo + base) = *(uint2*)ll;
}

__global__ __launch_bounds__(256) void gcn_agg_kernel(const float* __restrict__ convB) {
    int t = blockIdx.x * blockDim.x + threadIdx.x;
    int node = t >> 4;
    int lane = t & 15;
    if (node >= NN) return;

    float di = g_dinv[node];
    float w0 = di * di;
    const float4* mrow = (const float4*)(g_m + (size_t)node * HID);
    float4 a0 = mrow[lane], a1 = mrow[lane + 16], a2 = mrow[lane + 32];
    a0.x *= w0; a0.y *= w0; a0.z *= w0; a0.w *= w0;
    a1.x *= w0; a1.y *= w0; a1.z *= w0; a1.w *= w0;
    a2.x *= w0; a2.y *= w0; a2.z *= w0; a2.w *= w0;

    int beg = g_off[node], end = g_off[node + 1];
    for (int j = beg; j < end; j++) {
        int s = g_csr_src[j];
        float w = g_csr_w[j];
        const float4* ms = (const float4*)(g_m + (size_t)s * HID);
        f4_fma(a0, w, ms[lane]);
        f4_fma(a1, w, ms[lane + 16]);
        f4_fma(a2, w, ms[lane + 32]);
    }

    const float4* b4 = (const float4*)convB;
    float4 b0 = b4[lane], b1 = b4[lane + 16], b2 = b4[lane + 32];
    float4* hrow = (float4*)(g_h + (size_t)node * HID);
    float4 h0 = hrow[lane], h1 = hrow[lane + 16], h2 = hrow[lane + 32];
    h0.x += fmaxf(a0.x + b0.x, 0.f); h0.y += fmaxf(a0.y + b0.y, 0.f);
    h0.z += fmaxf(a0.z + b0.z, 0.f); h0.w += fmaxf(a0.w + b0.w, 0.f);
    h1.x += fmaxf(a1.x + b1.x, 0.f); h1.y += fmaxf(a1.y + b1.y, 0.f);
    h1.z += fmaxf(a1.z + b1.z, 0.f); h1.w += fmaxf(a1.w + b1.w, 0.f);
    h2.x += fmaxf(a2.x + b2.x, 0.f); h2.y += fmaxf(a2.y + b2.y, 0.f);
    h2.z += fmaxf(a2.z + b2.z, 0.f); h2.w += fmaxf(a2.w + b2.w, 0.f);
    hrow[lane] = h0; hrow[lane + 16] = h1; hrow[lane + 32] = h2;

    size_t base = (size_t)node * HID + lane * 4;
    split_store4(base, h0);
    split_store4(base + 64, h1);
    split_store4(base + 128, h2);
}

// ---------------------------------------------------------------------------
// Final head (unchanged from passing R3)
// ---------------------------------------------------------------------------
__global__ void head_final_kernel(
    const float* __restrict__ Wp3, const float* __restrict__ bp3,
    const float* __restrict__ Wr2, const float* __restrict__ br2,
    float* __restrict__ out)
{
    int w = (blockIdx.x * blockDim.x + threadIdx.x) >> 5;
    int lane = threadIdx.x & 31;
    if (w >= NN) return;
    const float* p2 = g_p2 + (size_t)w * 96;
    const float* rr = g_r + (size_t)w * 96;
    float a0 = 0.0f, a1 = 0.0f, ar = 0.0f;
    #pragma unroll
    for (int i = lane; i < 96; i += 32) {
        float v = p2[i];
        a0 = fmaf(v, Wp3[i * 2 + 0], a0);
        a1 = fmaf(v, Wp3[i * 2 + 1], a1);
        ar = fmaf(rr[i], Wr2[i], ar);
    }
    #pragma unroll
    for (int o = 16; o; o >>= 1) {
        a0 += __shfl_down_sync(0xFFFFFFFFu, a0, o);
        a1 += __shfl_down_sync(0xFFFFFFFFu, a1, o);
        ar += __shfl_down_sync(0xFFFFFFFFu, ar, o);
    }
    if (lane == 0) {
        float p0 = a0 + bp3[0];
        float p1 = a1 + bp3[1];
        float rad = 1.0f / (1.0f + expf(-(ar + br2[0])));
        float nrm = sqrtf(p0 * p0 + p1 * p1) + 1e-8f;
        float scale = rad / nrm;
        out[w * 2 + 0] = p0 * scale;
        out[w * 2 + 1] = p1 * scale;
    }
}

// ---------------------------------------------------------------------------
extern "C" void kernel_launch(void* const* d_in, const int* in_sizes, int n_in,
                              void* d_out, int out_size)
{
    const float *x, *Wp, *bp, *convW, *convB, *Wp1, *bp1, *Wp2, *bp2, *Wp3, *bp3;
    const float *Wr1, *br1, *Wr2, *br2;
    const int *ei;

    if (in_sizes[0] == NN * DIN) {
        x     = (const float*)d_in[0];
        ei    = (const int*)  d_in[1];
        Wp    = (const float*)d_in[2];  bp    = (const float*)d_in[3];
        convW = (const float*)d_in[4];  convB = (const float*)d_in[5];
        Wp1   = (const float*)d_in[6];  bp1   = (const float*)d_in[7];
        Wp2   = (const float*)d_in[8];  bp2   = (const float*)d_in[9];
        Wp3   = (const float*)d_in[10]; bp3   = (const float*)d_in[11];
        Wr1   = (const float*)d_in[12]; br1   = (const float*)d_in[13];
        Wr2   = (const float*)d_in[14]; br2   = (const float*)d_in[15];
    } else {
        Wp    = (const float*)d_in[0];
        Wp1   = (const float*)d_in[1];
        Wp2   = (const float*)d_in[2];
        Wp3   = (const float*)d_in[3];
        Wr1   = (const float*)d_in[4];
        Wr2   = (const float*)d_in[5];
        bp    = (const float*)d_in[6];
        bp1   = (const float*)d_in[7];
        bp2   = (const float*)d_in[8];
        bp3   = (const float*)d_in[9];
        br1   = (const float*)d_in[10];
        br2   = (const float*)d_in[11];
        convB = (const float*)d_in[12];
        convW = (const float*)d_in[13];
        ei    = (const int*)  d_in[14];
        x     = (const float*)d_in[15];
    }
    float* out = (float*)d_out;

    // resolve device-global scratch to REAL device pointers (GB300 ATS trap)
    float *p_h, *p_m, *p_p2, *p_r;
    __nv_bfloat16 *p_xh, *p_xl, *p_hh, *p_hl, *p_ph, *p_pl, *p_wh, *p_wl;
    cudaGetSymbolAddress((void**)&p_h,  g_h);
    cudaGetSymbolAddress((void**)&p_m,  g_m);
    cudaGetSymbolAddress((void**)&p_p2, g_p2);
    cudaGetSymbolAddress((void**)&p_r,  g_r);
    cudaGetSymbolAddress((void**)&p_xh, g_x_hi);
    cudaGetSymbolAddress((void**)&p_xl, g_x_lo);
    cudaGetSymbolAddress((void**)&p_hh, g_h_hi);
    cudaGetSymbolAddress((void**)&p_hl, g_h_lo);
    cudaGetSymbolAddress((void**)&p_ph, g_p_hi);
    cudaGetSymbolAddress((void**)&p_pl, g_p_lo);
    cudaGetSymbolAddress((void**)&p_wh, g_wt_hi);
    cudaGetSymbolAddress((void**)&p_wl, g_wt_lo);

    const int* src = ei;
    const int* dst = ei + NE;

    // CSR build
    zero_counts_kernel<<<(NN + 255) / 256, 256>>>();
    deg_count_kernel<<<(NE + 255) / 256, 256>>>(dst);
    scan_kernel<<<1, 1024>>>();
    dinv_kernel<<<(NN + 255) / 256, 256>>>();
    csr_fill_kernel<<<(NE + 255) / 256, 256>>>(src, dst);

    // operand prep: split x; transpose+split all GEMM weights
    split_kernel<<<(NN * DIN + 255) / 256, 256>>>(x, p_xh, p_xl, NN * DIN);
    tsplit_kernel<<<(DIN * HID + 255) / 256, 256>>>(Wp, p_wh + OW_P, p_wl + OW_P, DIN, HID);
    for (int l = 0; l < 4; l++)
        tsplit_kernel<<<(HID * HID + 255) / 256, 256>>>(
            convW + (size_t)l * HID * HID,
            p_wh + OW_CONV + l * HID * HID, p_wl + OW_CONV + l * HID * HID, HID, HID);
    tsplit_kernel<<<(HID * HID + 255) / 256, 256>>>(Wp1, p_wh + OW_P1, p_wl + OW_P1, HID, HID);
    tsplit_kernel<<<(HID * 96 + 255) / 256, 256>>>(Wp2, p_wh + OW_P2, p_wl + OW_P2, HID, 96);
    tsplit_kernel<<<(HID * 96 + 255) / 256, 256>>>(Wr1, p_wh + OW_R1, p_wl + OW_R1, HID, 96);

    int nblk = (NN + 127) / 128;
    size_t sm12 = (size_t)(2 * 128 * 40 + 2 * 192 * 40) * sizeof(__nv_bfloat16); // 51200
    size_t sm6  = (size_t)(2 * 128 * 40 + 2 * 96 * 40) * sizeof(__nv_bfloat16);  // 35840
    cudaFuncSetAttribute(gemm_tc<12>, cudaFuncAttributeMaxDynamicSharedMemorySize, (int)sm12);
    cudaFuncSetAttribute(gemm_tc<6>,  cudaFuncAttributeMaxDynamicSharedMemorySize, (int)sm6);

    // input projection: h = x @ Wp + bp (fp32 h + bf16 splits)
    gemm_tc<12><<<nblk, 256, sm12>>>(p_xh, p_xl, p_wh + OW_P, p_wl + OW_P,
                                     bp, 0, p_h, p_hh, p_hl, NN, DIN);

    // 4 GCN layers
    for (int l = 0; l < 4; l++) {
        gemm_tc<12><<<nblk, 256, sm12>>>(p_hh, p_hl,
                                         p_wh + OW_CONV + l * HID * HID,
                                         p_wl + OW_CONV + l * HID * HID,
                                         nullptr, 0, p_m, nullptr, nullptr, NN, HID);
        gcn_agg_kernel<<<(NN * 16 + 255) / 256, 256>>>(convB + (size_t)l * HID);
    }

    // heads
    gemm_tc<12><<<nblk, 256, sm12>>>(p_hh, p_hl, p_wh + OW_P1, p_wl + OW_P1,
                                     bp1, 1, nullptr, p_ph, p_pl, NN, HID);
    gemm_tc<6><<<nblk, 256, sm6>>>(p_ph, p_pl, p_wh + OW_P2, p_wl + OW_P2,
                                   bp2, 1, p_p2, nullptr, nullptr, NN, HID);
    gemm_tc<6><<<nblk, 256, sm6>>>(p_hh, p_hl, p_wh + OW_R1, p_wl + OW_R1,
                                   br1, 1, p_r, nullptr, nullptr, NN, HID);
    head_final_kernel<<<(NN * 32 + 255) / 256, 256>>>(Wp3, bp3, Wr2, br2, out);
}